// round 4
// baseline (speedup 1.0000x reference)
#include <cuda_runtime.h>

#define N_NODES  100000
#define N_EDGES  3200000
#define N_GRAPHS 1024
#define HID      64
#define NCLS     21

// ---- scratch (device globals; 128B-aligned so float4/red.v4 never trap) ----
__device__ __align__(128) float g_agg1[N_NODES];
__device__ __align__(128) float g_cnt [N_NODES];
__device__ __align__(128) float g_h1  [N_NODES * HID];
__device__ __align__(128) float g_agg2[N_NODES * HID];
__device__ __align__(128) float g_pool[N_GRAPHS * HID];
__device__ __align__(128) float g_gcnt[N_GRAPHS];

// ---- zero all scratch (re-run every replay) ----
__global__ void zero_kernel() {
    int i = blockIdx.x * blockDim.x + threadIdx.x;
    int stride = gridDim.x * blockDim.x;
    for (int j = i; j < N_NODES; j += stride) { g_agg1[j] = 0.0f; g_cnt[j] = 0.0f; }
    for (int j = i; j < N_NODES * HID; j += stride) g_agg2[j] = 0.0f;
    for (int j = i; j < N_GRAPHS * HID; j += stride) g_pool[j] = 0.0f;
    for (int j = i; j < N_GRAPHS; j += stride) g_gcnt[j] = 0.0f;
}

__device__ __forceinline__ int clamp_node(int i) {
    i = i < 0 ? 0 : i;
    return i >= N_NODES ? N_NODES - 1 : i;
}

// ---- layer-1 edge scatter: scalar features + degree count ----
__global__ void edge1_kernel(const float* __restrict__ x,
                             const int* __restrict__ ei) {
    int e = blockIdx.x * blockDim.x + threadIdx.x;
    if (e >= N_EDGES) return;
    int s = clamp_node(ei[e]);
    int d = clamp_node(ei[N_EDGES + e]);
    atomicAdd(&g_agg1[d], x[s]);
    atomicAdd(&g_cnt[d], 1.0f);
}

// ---- h1 = relu(mean_agg * W1l + b1 + x * W1r), feature dim 1 -> 64 ----
__global__ void h1_kernel(const float* __restrict__ x,
                          const float* __restrict__ W1l,
                          const float* __restrict__ b1,
                          const float* __restrict__ W1r) {
    int idx = blockIdx.x * blockDim.x + threadIdx.x;
    if (idx >= N_NODES * HID) return;
    int n = idx >> 6;
    int f = idx & 63;
    float agg = g_agg1[n] / fmaxf(g_cnt[n], 1.0f);
    float v = agg * W1l[f] + b1[f] + x[n] * W1r[f];
    g_h1[idx] = fmaxf(v, 0.0f);
}

// ---- layer-2 edge scatter: 16 threads/edge, float4 + red.global.add.v4 ----
// 32-bit indexing: total threads = 51.2M < 2^31.
__global__ void edge2_kernel(const int* __restrict__ ei) {
    unsigned t = blockIdx.x * blockDim.x + threadIdx.x;
    unsigned e = t >> 4;
    if (e >= N_EDGES) return;
    int q = (int)(t & 15u);
    int s = clamp_node(ei[e]);
    int d = clamp_node(ei[N_EDGES + e]);
    const float4 v = *(const float4*)&g_h1[s * HID + q * 4];
    float* dst = &g_agg2[d * HID + q * 4];
    asm volatile("red.global.add.v4.f32 [%0], {%1,%2,%3,%4};"
                 :: "l"(dst), "f"(v.x), "f"(v.y), "f"(v.z), "f"(v.w)
                 : "memory");
}

// ---- h2 = relu(mean_agg2 @ W2l + b2 + h1 @ W2r), fused with graph pooling ----
// 4 nodes per 256-thread block; 100000 = 4 * 25000 exactly.
__global__ void h2pool_kernel(const int* __restrict__ batch,
                              const float* __restrict__ W2l,
                              const float* __restrict__ b2,
                              const float* __restrict__ W2r) {
    __shared__ float sA[4][HID];
    __shared__ float sH[4][HID];
    int grp = threadIdx.x >> 6;
    int f   = threadIdx.x & 63;
    int n   = blockIdx.x * 4 + grp;

    float c = fmaxf(g_cnt[n], 1.0f);
    sA[grp][f] = g_agg2[n * HID + f] / c;
    sH[grp][f] = g_h1[n * HID + f];
    __syncthreads();

    float acc = b2[f];
#pragma unroll
    for (int k = 0; k < HID; k++) {
        acc += sA[grp][k] * W2l[k * HID + f];
        acc += sH[grp][k] * W2r[k * HID + f];
    }
    float h2 = fmaxf(acc, 0.0f);

    int bv = batch[n];
    int b = bv < 0 ? 0 : (bv >= N_GRAPHS ? N_GRAPHS - 1 : bv);
    atomicAdd(&g_pool[b * HID + f], h2);
    if (f == 0) atomicAdd(&g_gcnt[b], 1.0f);
}

// ---- classifier: out = mean_pool @ Wc + bc ----
__global__ void final_kernel(const float* __restrict__ Wc,
                             const float* __restrict__ bc,
                             float* __restrict__ out) {
    int g = blockIdx.x;
    int cid = threadIdx.x;
    if (cid >= NCLS) return;
    float inv = 1.0f / fmaxf(g_gcnt[g], 1.0f);
    float acc = bc[cid];
#pragma unroll
    for (int k = 0; k < HID; k++) {
        acc += g_pool[g * HID + k] * inv * Wc[k * NCLS + cid];
    }
    out[g * NCLS + cid] = acc;
}

extern "C" void kernel_launch(void* const* d_in, const int* in_sizes, int n_in,
                              void* d_out, int out_size) {
    const float* x    = (const float*)d_in[0];
    const int*   ei   = (const int*)d_in[1];
    const int*   bat  = (const int*)d_in[2];
    const float* W1l  = (const float*)d_in[3];
    const float* b1   = (const float*)d_in[4];
    const float* W1r  = (const float*)d_in[5];
    const float* W2l  = (const float*)d_in[6];
    const float* b2   = (const float*)d_in[7];
    const float* W2r  = (const float*)d_in[8];
    const float* Wc   = (const float*)d_in[9];
    const float* bc   = (const float*)d_in[10];
    float*       out  = (float*)d_out;

    (void)in_sizes; (void)n_in; (void)out_size;

    zero_kernel<<<6400, 256>>>();

    edge1_kernel<<<(N_EDGES + 255) / 256, 256>>>(x, ei);

    h1_kernel<<<(N_NODES * HID + 255) / 256, 256>>>(x, W1l, b1, W1r);

    {
        unsigned total = (unsigned)N_EDGES * 16u;
        unsigned blocks = (total + 255u) / 256u;
        edge2_kernel<<<blocks, 256>>>(ei);
    }

    h2pool_kernel<<<N_NODES / 4, 256>>>(bat, W2l, b2, W2r);

    final_kernel<<<N_GRAPHS, 32>>>(Wc, bc, out);
}

// round 5
// speedup vs baseline: 1.3261x; 1.3261x over previous
#include <cuda_runtime.h>

#define N_NODES  100000
#define N_EDGES  3200000
#define N_GRAPHS 1024
#define HID      64
#define NCLS     21
#define NBLK     391   // ceil(N_NODES / 256)

// ---- scratch ----
__device__ __align__(128) float g_agg1[N_NODES];
__device__ __align__(128) int   g_deg [N_NODES];
__device__ __align__(128) int   g_cursor[N_NODES];
__device__ __align__(128) int   g_row [N_NODES];      // CSR row starts
__device__ __align__(128) int   g_bsum[NBLK];
__device__ __align__(128) int   g_boff[NBLK];
__device__ __align__(128) int   g_csr [N_EDGES];      // src ids sorted by dst
__device__ __align__(128) float g_h1  [N_NODES * HID];
__device__ __align__(128) float g_agg2[N_NODES * HID]; // stores the MEAN directly
__device__ __align__(128) float g_pool[N_GRAPHS * HID];
__device__ __align__(128) float g_gcnt[N_GRAPHS];

__device__ __forceinline__ int clamp_node(int i) {
    i = i < 0 ? 0 : i;
    return i >= N_NODES ? N_NODES - 1 : i;
}

// ---- zero small scratch (h1/agg2 fully overwritten each run) ----
__global__ void zero_kernel() {
    int i = blockIdx.x * blockDim.x + threadIdx.x;
    int stride = gridDim.x * blockDim.x;
    for (int j = i; j < N_NODES; j += stride) {
        g_agg1[j] = 0.0f; g_deg[j] = 0; g_cursor[j] = 0;
    }
    for (int j = i; j < N_GRAPHS * HID; j += stride) g_pool[j] = 0.0f;
    for (int j = i; j < N_GRAPHS; j += stride) g_gcnt[j] = 0.0f;
}

// ---- hist: degree count (int) + layer-1 scalar aggregation ----
__global__ void hist_kernel(const float* __restrict__ x,
                            const int* __restrict__ ei) {
    int e = blockIdx.x * blockDim.x + threadIdx.x;
    if (e >= N_EDGES) return;
    int s = clamp_node(ei[e]);
    int d = clamp_node(ei[N_EDGES + e]);
    atomicAdd(&g_agg1[d], x[s]);
    atomicAdd(&g_deg[d], 1);
}

// ---- scan A: per-block sums of degree ----
__global__ void scanA_kernel() {
    __shared__ int s[256];
    int t = threadIdx.x;
    int i = blockIdx.x * 256 + t;
    s[t] = (i < N_NODES) ? g_deg[i] : 0;
    __syncthreads();
    for (int off = 128; off > 0; off >>= 1) {
        if (t < off) s[t] += s[t + off];
        __syncthreads();
    }
    if (t == 0) g_bsum[blockIdx.x] = s[0];
}

// ---- scan B: exclusive scan of NBLK block sums (single block, 512 thr) ----
__global__ void scanB_kernel() {
    __shared__ int s[512];
    int t = threadIdx.x;
    int v = (t < NBLK) ? g_bsum[t] : 0;
    s[t] = v;
    __syncthreads();
    for (int off = 1; off < 512; off <<= 1) {
        int tmp = 0;
        if (t >= off) tmp = s[t - off];
        __syncthreads();
        if (t >= off) s[t] += tmp;
        __syncthreads();
    }
    if (t < NBLK) g_boff[t] = s[t] - v;
}

// ---- scan C: intra-block exclusive scan + block offset -> row starts ----
__global__ void scanC_kernel() {
    __shared__ int s[256];
    int t = threadIdx.x;
    int i = blockIdx.x * 256 + t;
    int v = (i < N_NODES) ? g_deg[i] : 0;
    s[t] = v;
    __syncthreads();
    for (int off = 1; off < 256; off <<= 1) {
        int tmp = 0;
        if (t >= off) tmp = s[t - off];
        __syncthreads();
        if (t >= off) s[t] += tmp;
        __syncthreads();
    }
    if (i < N_NODES) g_row[i] = g_boff[blockIdx.x] + s[t] - v;
}

// ---- scatter: fill CSR (src ids grouped by dst) ----
__global__ void scatter_kernel(const int* __restrict__ ei) {
    int e = blockIdx.x * blockDim.x + threadIdx.x;
    if (e >= N_EDGES) return;
    int s = clamp_node(ei[e]);
    int d = clamp_node(ei[N_EDGES + e]);
    int pos = g_row[d] + atomicAdd(&g_cursor[d], 1);
    g_csr[pos] = s;
}

// ---- h1 = relu(mean_agg1 * W1l + b1 + x * W1r) ----
__global__ void h1_kernel(const float* __restrict__ x,
                          const float* __restrict__ W1l,
                          const float* __restrict__ b1,
                          const float* __restrict__ W1r) {
    int idx = blockIdx.x * blockDim.x + threadIdx.x;
    if (idx >= N_NODES * HID) return;
    int n = idx >> 6;
    int f = idx & 63;
    float agg = g_agg1[n] / fmaxf((float)g_deg[n], 1.0f);
    float v = agg * W1l[f] + b1[f] + x[n] * W1r[f];
    g_h1[idx] = fmaxf(v, 0.0f);
}

// ---- layer-2 aggregation via CSR gather (no atomics); writes the mean ----
// 4 nodes per 256-thread block, 64 threads (one feature each) per node.
__global__ void agg2_csr_kernel() {
    int grp = threadIdx.x >> 6;
    int f   = threadIdx.x & 63;
    int n   = blockIdx.x * 4 + grp;
    int start = g_row[n];
    int deg   = g_deg[n];
    int end   = start + deg;
    float acc = 0.0f;
    int j = start;
    for (; j + 4 <= end; j += 4) {
        int s0 = g_csr[j], s1 = g_csr[j + 1], s2 = g_csr[j + 2], s3 = g_csr[j + 3];
        float v0 = g_h1[s0 * HID + f];
        float v1 = g_h1[s1 * HID + f];
        float v2 = g_h1[s2 * HID + f];
        float v3 = g_h1[s3 * HID + f];
        acc += (v0 + v1) + (v2 + v3);
    }
    for (; j < end; j++) acc += g_h1[g_csr[j] * HID + f];
    g_agg2[n * HID + f] = acc / fmaxf((float)deg, 1.0f);
}

// ---- gcnt: nodes per graph ----
__global__ void gcnt_kernel(const int* __restrict__ batch) {
    int n = blockIdx.x * blockDim.x + threadIdx.x;
    if (n >= N_NODES) return;
    int b = batch[n];
    b = b < 0 ? 0 : (b >= N_GRAPHS ? N_GRAPHS - 1 : b);
    atomicAdd(&g_gcnt[b], 1.0f);
}

// ---- h2 = relu([agg2mean | h1] @ [W2l; W2r] + b2), tiled GEMM + fused pool ----
// Block: 64 nodes x 64 feats, 256 threads, 4x4 micro-tile per thread.
// K = 128 processed in two 64-chunks to fit static smem.
#define SASTR 68
__global__ void h2pool_gemm(const int* __restrict__ batch,
                            const float* __restrict__ W2l,
                            const float* __restrict__ b2,
                            const float* __restrict__ W2r) {
    __shared__ float sA[64 * SASTR];  // A_T chunk: [k][node], stride 68
    __shared__ float sB[64 * SASTR];  // B chunk:   [k][feat], stride 68
    __shared__ int   sBatch[64];

    int t  = threadIdx.x;
    int n0 = blockIdx.x * 64;
    int tx = t & 15;   // feature group (4 feats)
    int ty = t >> 4;   // node group (4 nodes)

    if (t < 64) {
        int n = n0 + t;
        int b = -1;
        if (n < N_NODES) {
            b = batch[n];
            b = b < 0 ? 0 : (b >= N_GRAPHS ? N_GRAPHS - 1 : b);
        }
        sBatch[t] = b;
    }

    float acc[4][4] = {};

#pragma unroll
    for (int ch = 0; ch < 2; ch++) {
        const float* Asrc = ch ? g_h1 : g_agg2;
        const float* Bsrc = ch ? W2r : W2l;
#pragma unroll
        for (int i = 0; i < 16; i++) {
            int idx = t + i * 256;
            int f = idx & 63, n = idx >> 6;
            float v = (n0 + n < N_NODES) ? Asrc[(n0 + n) * HID + f] : 0.0f;
            sA[f * SASTR + n] = v;
        }
#pragma unroll
        for (int i = 0; i < 16; i++) {
            int idx = t + i * 256;
            int f = idx & 63, k = idx >> 6;
            sB[k * SASTR + f] = Bsrc[k * HID + f];
        }
        __syncthreads();
#pragma unroll
        for (int k = 0; k < 64; k++) {
            float4 a = *(const float4*)&sA[k * SASTR + ty * 4];
            float4 b = *(const float4*)&sB[k * SASTR + tx * 4];
            acc[0][0] += a.x * b.x; acc[0][1] += a.x * b.y; acc[0][2] += a.x * b.z; acc[0][3] += a.x * b.w;
            acc[1][0] += a.y * b.x; acc[1][1] += a.y * b.y; acc[1][2] += a.y * b.z; acc[1][3] += a.y * b.w;
            acc[2][0] += a.z * b.x; acc[2][1] += a.z * b.y; acc[2][2] += a.z * b.z; acc[2][3] += a.z * b.w;
            acc[3][0] += a.w * b.x; acc[3][1] += a.w * b.y; acc[3][2] += a.w * b.z; acc[3][3] += a.w * b.w;
        }
        __syncthreads();
    }

    // bias + relu, stage h2 into sA as [node][feat] (stride 68)
#pragma unroll
    for (int i = 0; i < 4; i++) {
#pragma unroll
        for (int j = 0; j < 4; j++) {
            float v = fmaxf(acc[i][j] + b2[tx * 4 + j], 0.0f);
            sA[(ty * 4 + i) * SASTR + tx * 4 + j] = v;
        }
    }
    __syncthreads();

    // pooled reduction: thread (g, f) handles nodes g*16..g*16+15, feature f.
    // batch is sorted -> run-accumulate, one atomic per run.
    {
        int f = t & 63;
        int g = t >> 6;
        int cur = -2;
        float racc = 0.0f;
#pragma unroll
        for (int i = 0; i < 16; i++) {
            int n = g * 16 + i;
            int b = sBatch[n];
            if (b != cur) {
                if (cur >= 0) atomicAdd(&g_pool[cur * HID + f], racc);
                racc = 0.0f;
                cur = b;
            }
            if (b >= 0) racc += sA[n * SASTR + f];
        }
        if (cur >= 0) atomicAdd(&g_pool[cur * HID + f], racc);
    }
}

// ---- classifier ----
__global__ void final_kernel(const float* __restrict__ Wc,
                             const float* __restrict__ bc,
                             float* __restrict__ out) {
    int g = blockIdx.x;
    int cid = threadIdx.x;
    if (cid >= NCLS) return;
    float inv = 1.0f / fmaxf(g_gcnt[g], 1.0f);
    float acc = bc[cid];
#pragma unroll
    for (int k = 0; k < HID; k++) {
        acc += g_pool[g * HID + k] * inv * Wc[k * NCLS + cid];
    }
    out[g * NCLS + cid] = acc;
}

extern "C" void kernel_launch(void* const* d_in, const int* in_sizes, int n_in,
                              void* d_out, int out_size) {
    const float* x    = (const float*)d_in[0];
    const int*   ei   = (const int*)d_in[1];
    const int*   bat  = (const int*)d_in[2];
    const float* W1l  = (const float*)d_in[3];
    const float* b1   = (const float*)d_in[4];
    const float* W1r  = (const float*)d_in[5];
    const float* W2l  = (const float*)d_in[6];
    const float* b2   = (const float*)d_in[7];
    const float* W2r  = (const float*)d_in[8];
    const float* Wc   = (const float*)d_in[9];
    const float* bc   = (const float*)d_in[10];
    float*       out  = (float*)d_out;

    (void)in_sizes; (void)n_in; (void)out_size;

    zero_kernel<<<2048, 256>>>();
    hist_kernel<<<(N_EDGES + 255) / 256, 256>>>(x, ei);
    scanA_kernel<<<NBLK, 256>>>();
    scanB_kernel<<<1, 512>>>();
    scanC_kernel<<<NBLK, 256>>>();
    scatter_kernel<<<(N_EDGES + 255) / 256, 256>>>(ei);
    h1_kernel<<<(N_NODES * HID + 255) / 256, 256>>>(x, W1l, b1, W1r);
    gcnt_kernel<<<(N_NODES + 255) / 256, 256>>>(bat);
    agg2_csr_kernel<<<N_NODES / 4, 256>>>();
    h2pool_gemm<<<(N_NODES + 63) / 64, 256>>>(bat, W2l, b2, W2r);
    final_kernel<<<N_GRAPHS, 32>>>(Wc, bc, out);
}

// round 6
// speedup vs baseline: 1.7569x; 1.3249x over previous
#include <cuda_runtime.h>

#define N_NODES  100000
#define N_EDGES  3200000
#define N_GRAPHS 1024
#define HID      64
#define NCLS     21
#define NBLK     391   // ceil(N_NODES / 256)

// ---- scratch ----
__device__ __align__(128) int    g_deg [N_NODES];
__device__ __align__(128) int    g_cursor[N_NODES];
__device__ __align__(128) int    g_row [N_NODES];      // CSR row starts
__device__ __align__(128) int    g_bsum[NBLK];
__device__ __align__(128) int    g_boff[NBLK];
__device__ __align__(128) int    g_csr [N_EDGES];      // src ids grouped by dst
__device__ __align__(128) float2 g_nf  [N_NODES];      // (mean1, x) per node
__device__ __align__(128) float  g_agg2[N_NODES * HID]; // layer-2 neighbor MEAN
__device__ __align__(128) float  g_pool[N_GRAPHS * HID];
__device__ __align__(128) float  g_gcnt[N_GRAPHS];

__device__ __forceinline__ int clamp_node(int i) {
    i = i < 0 ? 0 : i;
    return i >= N_NODES ? N_NODES - 1 : i;
}

// ---- zero (only what is accumulated into) ----
__global__ void zero_kernel() {
    int i = blockIdx.x * blockDim.x + threadIdx.x;
    int stride = gridDim.x * blockDim.x;
    for (int j = i; j < N_NODES; j += stride) { g_deg[j] = 0; g_cursor[j] = 0; }
    for (int j = i; j < N_GRAPHS * HID; j += stride) g_pool[j] = 0.0f;
    for (int j = i; j < N_GRAPHS; j += stride) g_gcnt[j] = 0.0f;
}

// ---- degree histogram (dst only) ----
__global__ void hist_kernel(const int* __restrict__ ei) {
    int e = blockIdx.x * blockDim.x + threadIdx.x;
    if (e >= N_EDGES) return;
    int d = clamp_node(ei[N_EDGES + e]);
    atomicAdd(&g_deg[d], 1);
}

// ---- scan A: per-block sums ----
__global__ void scanA_kernel() {
    __shared__ int s[256];
    int t = threadIdx.x;
    int i = blockIdx.x * 256 + t;
    s[t] = (i < N_NODES) ? g_deg[i] : 0;
    __syncthreads();
    for (int off = 128; off > 0; off >>= 1) {
        if (t < off) s[t] += s[t + off];
        __syncthreads();
    }
    if (t == 0) g_bsum[blockIdx.x] = s[0];
}

// ---- scan B: exclusive scan of block sums ----
__global__ void scanB_kernel() {
    __shared__ int s[512];
    int t = threadIdx.x;
    int v = (t < NBLK) ? g_bsum[t] : 0;
    s[t] = v;
    __syncthreads();
    for (int off = 1; off < 512; off <<= 1) {
        int tmp = 0;
        if (t >= off) tmp = s[t - off];
        __syncthreads();
        if (t >= off) s[t] += tmp;
        __syncthreads();
    }
    if (t < NBLK) g_boff[t] = s[t] - v;
}

// ---- scan C: row starts ----
__global__ void scanC_kernel() {
    __shared__ int s[256];
    int t = threadIdx.x;
    int i = blockIdx.x * 256 + t;
    int v = (i < N_NODES) ? g_deg[i] : 0;
    s[t] = v;
    __syncthreads();
    for (int off = 1; off < 256; off <<= 1) {
        int tmp = 0;
        if (t >= off) tmp = s[t - off];
        __syncthreads();
        if (t >= off) s[t] += tmp;
        __syncthreads();
    }
    if (i < N_NODES) g_row[i] = g_boff[blockIdx.x] + s[t] - v;
}

// ---- scatter: fill CSR ----
__global__ void scatter_kernel(const int* __restrict__ ei) {
    int e = blockIdx.x * blockDim.x + threadIdx.x;
    if (e >= N_EDGES) return;
    int s = clamp_node(ei[e]);
    int d = clamp_node(ei[N_EDGES + e]);
    int pos = g_row[d] + atomicAdd(&g_cursor[d], 1);
    g_csr[pos] = s;
}

// ---- nf: per-node (mean of neighbor x, own x). Warp per node. ----
__global__ void nf_kernel(const float* __restrict__ x) {
    int wid  = threadIdx.x >> 5;
    int lane = threadIdx.x & 31;
    int n = blockIdx.x * 8 + wid;
    if (n >= N_NODES) return;
    int start = g_row[n], deg = g_deg[n], end = start + deg;
    float sum = 0.0f;
    for (int idx = start + lane; idx < end; idx += 32)
        sum += x[g_csr[idx]];
#pragma unroll
    for (int o = 16; o > 0; o >>= 1)
        sum += __shfl_xor_sync(0xffffffffu, sum, o);
    if (lane == 0)
        g_nf[n] = make_float2(sum / fmaxf((float)deg, 1.0f), x[n]);
}

// ---- layer-2 aggregation fused with on-the-fly h1. Warp per node. ----
// h1[s][f] = relu(mean1_s*W1l[f] + x_s*W1r[f] + b1[f]); agg2[n] = mean over nbrs.
__global__ void agg2_fused_kernel(const float* __restrict__ W1l,
                                  const float* __restrict__ b1,
                                  const float* __restrict__ W1r) {
    int wid  = threadIdx.x >> 5;
    int lane = threadIdx.x & 31;
    int n = blockIdx.x * 8 + wid;
    if (n >= N_NODES) return;

    float wl0 = W1l[lane],      wr0 = W1r[lane],      bb0 = b1[lane];
    float wl1 = W1l[lane + 32], wr1 = W1r[lane + 32], bb1 = b1[lane + 32];

    int start = g_row[n], deg = g_deg[n], end = start + deg;
    float acc0 = 0.0f, acc1 = 0.0f;

    for (int j = start; j < end; j += 32) {
        int idx = j + lane;
        int s = (idx < end) ? g_csr[idx] : 0;
        float2 nf = g_nf[s];
        int m = end - j; if (m > 32) m = 32;
        if (m == 32) {
#pragma unroll
            for (int jj = 0; jj < 32; jj++) {
                float a  = __shfl_sync(0xffffffffu, nf.x, jj);
                float xx = __shfl_sync(0xffffffffu, nf.y, jj);
                acc0 += fmaxf(fmaf(a, wl0, fmaf(xx, wr0, bb0)), 0.0f);
                acc1 += fmaxf(fmaf(a, wl1, fmaf(xx, wr1, bb1)), 0.0f);
            }
        } else {
            for (int jj = 0; jj < m; jj++) {
                float a  = __shfl_sync(0xffffffffu, nf.x, jj);
                float xx = __shfl_sync(0xffffffffu, nf.y, jj);
                acc0 += fmaxf(fmaf(a, wl0, fmaf(xx, wr0, bb0)), 0.0f);
                acc1 += fmaxf(fmaf(a, wl1, fmaf(xx, wr1, bb1)), 0.0f);
            }
        }
    }
    float inv = 1.0f / fmaxf((float)deg, 1.0f);
    g_agg2[n * HID + lane]      = acc0 * inv;
    g_agg2[n * HID + lane + 32] = acc1 * inv;
}

// ---- gcnt: nodes per graph ----
__global__ void gcnt_kernel(const int* __restrict__ batch) {
    int n = blockIdx.x * blockDim.x + threadIdx.x;
    if (n >= N_NODES) return;
    int b = batch[n];
    b = b < 0 ? 0 : (b >= N_GRAPHS ? N_GRAPHS - 1 : b);
    atomicAdd(&g_gcnt[b], 1.0f);
}

// ---- h2 = relu([agg2 | h1(on-the-fly)] @ [W2l; W2r] + b2) + fused pooling ----
#define SASTR 68
__global__ void h2pool_gemm(const int* __restrict__ batch,
                            const float* __restrict__ W2l,
                            const float* __restrict__ b2,
                            const float* __restrict__ W2r,
                            const float* __restrict__ W1l,
                            const float* __restrict__ b1,
                            const float* __restrict__ W1r) {
    __shared__ float  sA[64 * SASTR];  // A_T chunk: [k][node]
    __shared__ float  sB[64 * SASTR];  // B chunk:   [k][feat]
    __shared__ int    sBatch[64];
    __shared__ float2 sNF[64];

    int t  = threadIdx.x;
    int n0 = blockIdx.x * 64;
    int tx = t & 15;
    int ty = t >> 4;

    if (t < 64) {
        int n = n0 + t;
        int b = -1;
        float2 nf = make_float2(0.0f, 0.0f);
        if (n < N_NODES) {
            b = batch[n];
            b = b < 0 ? 0 : (b >= N_GRAPHS ? N_GRAPHS - 1 : b);
            nf = g_nf[n];
        }
        sBatch[t] = b;
        sNF[t] = nf;
    }
    __syncthreads();

    float acc[4][4] = {};

#pragma unroll
    for (int ch = 0; ch < 2; ch++) {
        const float* Bsrc = ch ? W2r : W2l;
        if (ch == 0) {
#pragma unroll
            for (int i = 0; i < 16; i++) {
                int idx = t + i * 256;
                int f = idx & 63, n = idx >> 6;
                float v = (n0 + n < N_NODES) ? g_agg2[(n0 + n) * HID + f] : 0.0f;
                sA[f * SASTR + n] = v;
            }
        } else {
#pragma unroll
            for (int i = 0; i < 16; i++) {
                int idx = t + i * 256;
                int f = idx & 63, n = idx >> 6;
                float2 nf = sNF[n];
                float v = fmaxf(fmaf(nf.x, W1l[f], fmaf(nf.y, W1r[f], b1[f])), 0.0f);
                if (n0 + n >= N_NODES) v = 0.0f;
                sA[f * SASTR + n] = v;
            }
        }
#pragma unroll
        for (int i = 0; i < 16; i++) {
            int idx = t + i * 256;
            int f = idx & 63, k = idx >> 6;
            sB[k * SASTR + f] = Bsrc[k * HID + f];
        }
        __syncthreads();
#pragma unroll
        for (int k = 0; k < 64; k++) {
            float4 a = *(const float4*)&sA[k * SASTR + ty * 4];
            float4 b = *(const float4*)&sB[k * SASTR + tx * 4];
            acc[0][0] += a.x * b.x; acc[0][1] += a.x * b.y; acc[0][2] += a.x * b.z; acc[0][3] += a.x * b.w;
            acc[1][0] += a.y * b.x; acc[1][1] += a.y * b.y; acc[1][2] += a.y * b.z; acc[1][3] += a.y * b.w;
            acc[2][0] += a.z * b.x; acc[2][1] += a.z * b.y; acc[2][2] += a.z * b.z; acc[2][3] += a.z * b.w;
            acc[3][0] += a.w * b.x; acc[3][1] += a.w * b.y; acc[3][2] += a.w * b.z; acc[3][3] += a.w * b.w;
        }
        __syncthreads();
    }

    // bias + relu, stage h2 into sA as [node][feat]
#pragma unroll
    for (int i = 0; i < 4; i++) {
#pragma unroll
        for (int j = 0; j < 4; j++) {
            float v = fmaxf(acc[i][j] + b2[tx * 4 + j], 0.0f);
            sA[(ty * 4 + i) * SASTR + tx * 4 + j] = v;
        }
    }
    __syncthreads();

    // pooled reduction: thread (g, f): nodes g*16..g*16+15, feature f.
    {
        int f = t & 63;
        int g = t >> 6;
        int cur = -2;
        float racc = 0.0f;
#pragma unroll
        for (int i = 0; i < 16; i++) {
            int n = g * 16 + i;
            int b = sBatch[n];
            if (b != cur) {
                if (cur >= 0) atomicAdd(&g_pool[cur * HID + f], racc);
                racc = 0.0f;
                cur = b;
            }
            if (b >= 0) racc += sA[n * SASTR + f];
        }
        if (cur >= 0) atomicAdd(&g_pool[cur * HID + f], racc);
    }
}

// ---- classifier ----
__global__ void final_kernel(const float* __restrict__ Wc,
                             const float* __restrict__ bc,
                             float* __restrict__ out) {
    int g = blockIdx.x;
    int cid = threadIdx.x;
    if (cid >= NCLS) return;
    float inv = 1.0f / fmaxf(g_gcnt[g], 1.0f);
    float acc = bc[cid];
#pragma unroll
    for (int k = 0; k < HID; k++) {
        acc += g_pool[g * HID + k] * inv * Wc[k * NCLS + cid];
    }
    out[g * NCLS + cid] = acc;
}

extern "C" void kernel_launch(void* const* d_in, const int* in_sizes, int n_in,
                              void* d_out, int out_size) {
    const float* x    = (const float*)d_in[0];
    const int*   ei   = (const int*)d_in[1];
    const int*   bat  = (const int*)d_in[2];
    const float* W1l  = (const float*)d_in[3];
    const float* b1   = (const float*)d_in[4];
    const float* W1r  = (const float*)d_in[5];
    const float* W2l  = (const float*)d_in[6];
    const float* b2   = (const float*)d_in[7];
    const float* W2r  = (const float*)d_in[8];
    const float* Wc   = (const float*)d_in[9];
    const float* bc   = (const float*)d_in[10];
    float*       out  = (float*)d_out;

    (void)in_sizes; (void)n_in; (void)out_size;

    zero_kernel<<<1024, 256>>>();
    hist_kernel<<<(N_EDGES + 255) / 256, 256>>>(ei);
    scanA_kernel<<<NBLK, 256>>>();
    scanB_kernel<<<1, 512>>>();
    scanC_kernel<<<NBLK, 256>>>();
    scatter_kernel<<<(N_EDGES + 255) / 256, 256>>>(ei);
    nf_kernel<<<12500, 256>>>(x);
    gcnt_kernel<<<(N_NODES + 255) / 256, 256>>>(bat);
    agg2_fused_kernel<<<12500, 256>>>(W1l, b1, W1r);
    h2pool_gemm<<<(N_NODES + 63) / 64, 256>>>(bat, W2l, b2, W2r, W1l, b1, W1r);
    final_kernel<<<N_GRAPHS, 32>>>(Wc, bc, out);
}

// round 7
// speedup vs baseline: 1.8688x; 1.0637x over previous
#include <cuda_runtime.h>

#define N_NODES  100000
#define N_EDGES  3200000
#define N_GRAPHS 1024
#define HID      64
#define NCLS     21
#define NBLK     391   // ceil(N_NODES / 256)

typedef unsigned long long ull;

// ---- scratch ----
__device__ __align__(128) int    g_deg [N_NODES];
__device__ __align__(128) int    g_cursor[N_NODES];
__device__ __align__(128) int    g_row [N_NODES];      // CSR row starts
__device__ __align__(128) int    g_bsum[NBLK];
__device__ __align__(128) int    g_boff[NBLK];
__device__ __align__(128) int    g_csr [N_EDGES];      // src ids grouped by dst
__device__ __align__(128) float2 g_nf  [N_NODES];      // (mean1, x) per node
__device__ __align__(128) float  g_pool[N_GRAPHS * HID];
__device__ __align__(128) float  g_gcnt[N_GRAPHS];

__device__ __forceinline__ int clamp_node(int i) {
    i = i < 0 ? 0 : i;
    return i >= N_NODES ? N_NODES - 1 : i;
}

// ---- packed fp32x2 helpers (Blackwell 2x fp32 path) ----
__device__ __forceinline__ ull pk2(float lo, float hi) {
    ull d; asm("mov.b64 %0, {%1, %2};" : "=l"(d) : "f"(lo), "f"(hi)); return d;
}
__device__ __forceinline__ ull fma2(ull a, ull b, ull c) {
    ull d; asm("fma.rn.f32x2 %0, %1, %2, %3;" : "=l"(d) : "l"(a), "l"(b), "l"(c)); return d;
}
__device__ __forceinline__ float2 unpk2(ull v) {
    float lo, hi; asm("mov.b64 {%0, %1}, %2;" : "=f"(lo), "=f"(hi) : "l"(v));
    return make_float2(lo, hi);
}

// ---- zero (only what is accumulated into) ----
__global__ void zero_kernel() {
    int i = blockIdx.x * blockDim.x + threadIdx.x;
    int stride = gridDim.x * blockDim.x;
    for (int j = i; j < N_NODES; j += stride) g_deg[j] = 0;
    for (int j = i; j < N_GRAPHS * HID; j += stride) g_pool[j] = 0.0f;
    for (int j = i; j < N_GRAPHS; j += stride) g_gcnt[j] = 0.0f;
}

// ---- degree histogram (dst only) + fused graph-count histogram ----
__global__ void hist_kernel(const int* __restrict__ ei,
                            const int* __restrict__ batch) {
    int e = blockIdx.x * blockDim.x + threadIdx.x;
    if (e < N_NODES) {
        int b = batch[e];
        b = b < 0 ? 0 : (b >= N_GRAPHS ? N_GRAPHS - 1 : b);
        atomicAdd(&g_gcnt[b], 1.0f);
    }
    if (e >= N_EDGES) return;
    int d = clamp_node(ei[N_EDGES + e]);
    atomicAdd(&g_deg[d], 1);
}

// ---- scan A: per-block sums ----
__global__ void scanA_kernel() {
    __shared__ int s[256];
    int t = threadIdx.x;
    int i = blockIdx.x * 256 + t;
    s[t] = (i < N_NODES) ? g_deg[i] : 0;
    __syncthreads();
    for (int off = 128; off > 0; off >>= 1) {
        if (t < off) s[t] += s[t + off];
        __syncthreads();
    }
    if (t == 0) g_bsum[blockIdx.x] = s[0];
}

// ---- scan B: exclusive scan of block sums ----
__global__ void scanB_kernel() {
    __shared__ int s[512];
    int t = threadIdx.x;
    int v = (t < NBLK) ? g_bsum[t] : 0;
    s[t] = v;
    __syncthreads();
    for (int off = 1; off < 512; off <<= 1) {
        int tmp = 0;
        if (t >= off) tmp = s[t - off];
        __syncthreads();
        if (t >= off) s[t] += tmp;
        __syncthreads();
    }
    if (t < NBLK) g_boff[t] = s[t] - v;
}

// ---- scan C: row starts (also seeds the scatter cursor) ----
__global__ void scanC_kernel() {
    __shared__ int s[256];
    int t = threadIdx.x;
    int i = blockIdx.x * 256 + t;
    int v = (i < N_NODES) ? g_deg[i] : 0;
    s[t] = v;
    __syncthreads();
    for (int off = 1; off < 256; off <<= 1) {
        int tmp = 0;
        if (t >= off) tmp = s[t - off];
        __syncthreads();
        if (t >= off) s[t] += tmp;
        __syncthreads();
    }
    if (i < N_NODES) {
        int r = g_boff[blockIdx.x] + s[t] - v;
        g_row[i] = r;
        g_cursor[i] = r;
    }
}

// ---- scatter: fill CSR (cursor pre-seeded with row start) ----
__global__ void scatter_kernel(const int* __restrict__ ei) {
    int e = blockIdx.x * blockDim.x + threadIdx.x;
    if (e >= N_EDGES) return;
    int s = clamp_node(ei[e]);
    int d = clamp_node(ei[N_EDGES + e]);
    int pos = atomicAdd(&g_cursor[d], 1);
    g_csr[pos] = s;
}

// ---- nf: per-node (mean of neighbor x, own x). Warp per node. ----
__global__ void nf_kernel(const float* __restrict__ x) {
    int wid  = threadIdx.x >> 5;
    int lane = threadIdx.x & 31;
    int n = blockIdx.x * 8 + wid;
    if (n >= N_NODES) return;
    int start = g_row[n], deg = g_deg[n], end = start + deg;
    float sum = 0.0f;
    for (int idx = start + lane; idx < end; idx += 32)
        sum += x[g_csr[idx]];
#pragma unroll
    for (int o = 16; o > 0; o >>= 1)
        sum += __shfl_xor_sync(0xffffffffu, sum, o);
    if (lane == 0)
        g_nf[n] = make_float2(sum / fmaxf((float)deg, 1.0f), x[n]);
}

// ==== fused: agg2 (in-block, via CSR + on-the-fly h1) -> GEMM -> relu -> pool ====
// Block = 64 nodes. Phase A: 8 warps x 8 nodes compute the neighbor-mean of h1
// directly into sA (feature-major). Phase B: [agg2 | h1] @ [W2l; W2r] with
// packed f32x2 FMA. Phase C: bias+relu, batched pooling atomics.
#define SASTR 68
__global__ __launch_bounds__(256) void h2pool_gemm(
        const int* __restrict__ batch,
        const float* __restrict__ W2l,
        const float* __restrict__ b2,
        const float* __restrict__ W2r,
        const float* __restrict__ W1l,
        const float* __restrict__ b1,
        const float* __restrict__ W1r) {
    __shared__ __align__(16) float sA[64 * SASTR];  // [k][node]
    __shared__ __align__(16) float sB[64 * SASTR];  // [k][feat]
    __shared__ int    sBatch[64];
    __shared__ float2 sNF[64];

    int t    = threadIdx.x;
    int lane = t & 31;
    int wid  = t >> 5;
    int n0   = blockIdx.x * 64;
    int tx   = t & 15;
    int ty   = t >> 4;

    if (t < 64) {
        int n = n0 + t;
        int b = -1;
        float2 nf = make_float2(0.0f, 0.0f);
        if (n < N_NODES) {
            b = batch[n];
            b = b < 0 ? 0 : (b >= N_GRAPHS ? N_GRAPHS - 1 : b);
            nf = g_nf[n];
        }
        sBatch[t] = b;
        sNF[t] = nf;
    }

    // fill sB with W2l while phase A runs
#pragma unroll
    for (int i = 0; i < 16; i++) {
        int idx = t + i * 256;
        int f = idx & 63, k = idx >> 6;
        sB[k * SASTR + f] = W2l[k * HID + f];
    }

    // ---- Phase A: per-warp agg2 into sA (transposed) ----
    {
        float wl0 = W1l[lane],      wr0 = W1r[lane],      bb0 = b1[lane];
        float wl1 = W1l[lane + 32], wr1 = W1r[lane + 32], bb1 = b1[lane + 32];
#pragma unroll 1
        for (int r = 0; r < 8; r++) {
            int nl = wid * 8 + r;
            int n  = n0 + nl;
            float acc0 = 0.0f, acc1 = 0.0f;
            int deg = 0;
            if (n < N_NODES) {
                int start = g_row[n];
                deg = g_deg[n];
                int end = start + deg;
                for (int j = start; j < end; j += 32) {
                    int idx = j + lane;
                    int s = (idx < end) ? g_csr[idx] : 0;
                    float2 nf = g_nf[s];
                    int m = end - j; if (m > 32) m = 32;
                    if (m == 32) {
#pragma unroll
                        for (int jj = 0; jj < 32; jj++) {
                            float a  = __shfl_sync(0xffffffffu, nf.x, jj);
                            float xx = __shfl_sync(0xffffffffu, nf.y, jj);
                            acc0 += fmaxf(fmaf(a, wl0, fmaf(xx, wr0, bb0)), 0.0f);
                            acc1 += fmaxf(fmaf(a, wl1, fmaf(xx, wr1, bb1)), 0.0f);
                        }
                    } else {
                        for (int jj = 0; jj < m; jj++) {
                            float a  = __shfl_sync(0xffffffffu, nf.x, jj);
                            float xx = __shfl_sync(0xffffffffu, nf.y, jj);
                            acc0 += fmaxf(fmaf(a, wl0, fmaf(xx, wr0, bb0)), 0.0f);
                            acc1 += fmaxf(fmaf(a, wl1, fmaf(xx, wr1, bb1)), 0.0f);
                        }
                    }
                }
            }
            float inv = 1.0f / fmaxf((float)deg, 1.0f);
            sA[lane * SASTR + nl]        = acc0 * inv;
            sA[(lane + 32) * SASTR + nl] = acc1 * inv;
        }
    }
    __syncthreads();

    // ---- Phase B: GEMM, 2 K-chunks, packed f32x2 FMA ----
    ull acc2[4][2] = {};
#pragma unroll
    for (int ch = 0; ch < 2; ch++) {
#pragma unroll
        for (int k = 0; k < 64; k++) {
            float4 a = *(const float4*)&sA[k * SASTR + ty * 4];
            ulonglong2 b = *(const ulonglong2*)&sB[k * SASTR + tx * 4];
            ull a0 = pk2(a.x, a.x), a1 = pk2(a.y, a.y);
            ull a2 = pk2(a.z, a.z), a3 = pk2(a.w, a.w);
            acc2[0][0] = fma2(a0, b.x, acc2[0][0]); acc2[0][1] = fma2(a0, b.y, acc2[0][1]);
            acc2[1][0] = fma2(a1, b.x, acc2[1][0]); acc2[1][1] = fma2(a1, b.y, acc2[1][1]);
            acc2[2][0] = fma2(a2, b.x, acc2[2][0]); acc2[2][1] = fma2(a2, b.y, acc2[2][1]);
            acc2[3][0] = fma2(a3, b.x, acc2[3][0]); acc2[3][1] = fma2(a3, b.y, acc2[3][1]);
        }
        __syncthreads();
        if (ch == 0) {
            // refill sA with on-the-fly h1, sB with W2r
#pragma unroll
            for (int i = 0; i < 16; i++) {
                int idx = t + i * 256;
                int f = idx & 63, n = idx >> 6;
                float2 nf = sNF[n];
                float v = fmaxf(fmaf(nf.x, W1l[f], fmaf(nf.y, W1r[f], b1[f])), 0.0f);
                if (n0 + n >= N_NODES) v = 0.0f;
                sA[f * SASTR + n] = v;
            }
#pragma unroll
            for (int i = 0; i < 16; i++) {
                int idx = t + i * 256;
                int f = idx & 63, k = idx >> 6;
                sB[k * SASTR + f] = W2r[k * HID + f];
            }
            __syncthreads();
        }
    }

    // ---- Phase C: bias + relu -> sA [node][feat], then batched pooling ----
#pragma unroll
    for (int i = 0; i < 4; i++) {
        float2 p0 = unpk2(acc2[i][0]);
        float2 p1 = unpk2(acc2[i][1]);
        int nrow = (ty * 4 + i) * SASTR + tx * 4;
        sA[nrow + 0] = fmaxf(p0.x + b2[tx * 4 + 0], 0.0f);
        sA[nrow + 1] = fmaxf(p0.y + b2[tx * 4 + 1], 0.0f);
        sA[nrow + 2] = fmaxf(p1.x + b2[tx * 4 + 2], 0.0f);
        sA[nrow + 3] = fmaxf(p1.y + b2[tx * 4 + 3], 0.0f);
    }
    __syncthreads();

    {
        int f = t & 63;
        int g = t >> 6;
        int cur = -2;
        float racc = 0.0f;
#pragma unroll
        for (int i = 0; i < 16; i++) {
            int n = g * 16 + i;
            int b = sBatch[n];
            if (b != cur) {
                if (cur >= 0) atomicAdd(&g_pool[cur * HID + f], racc);
                racc = 0.0f;
                cur = b;
            }
            if (b >= 0) racc += sA[n * SASTR + f];
        }
        if (cur >= 0) atomicAdd(&g_pool[cur * HID + f], racc);
    }
}

// ---- classifier ----
__global__ void final_kernel(const float* __restrict__ Wc,
                             const float* __restrict__ bc,
                             float* __restrict__ out) {
    int g = blockIdx.x;
    int cid = threadIdx.x;
    if (cid >= NCLS) return;
    float inv = 1.0f / fmaxf(g_gcnt[g], 1.0f);
    float acc = bc[cid];
#pragma unroll
    for (int k = 0; k < HID; k++) {
        acc += g_pool[g * HID + k] * inv * Wc[k * NCLS + cid];
    }
    out[g * NCLS + cid] = acc;
}

extern "C" void kernel_launch(void* const* d_in, const int* in_sizes, int n_in,
                              void* d_out, int out_size) {
    const float* x    = (const float*)d_in[0];
    const int*   ei   = (const int*)d_in[1];
    const int*   bat  = (const int*)d_in[2];
    const float* W1l  = (const float*)d_in[3];
    const float* b1   = (const float*)d_in[4];
    const float* W1r  = (const float*)d_in[5];
    const float* W2l  = (const float*)d_in[6];
    const float* b2   = (const float*)d_in[7];
    const float* W2r  = (const float*)d_in[8];
    const float* Wc   = (const float*)d_in[9];
    const float* bc   = (const float*)d_in[10];
    float*       out  = (float*)d_out;

    (void)in_sizes; (void)n_in; (void)out_size;

    zero_kernel<<<1024, 256>>>();
    hist_kernel<<<(N_EDGES + 255) / 256, 256>>>(ei, bat);
    scanA_kernel<<<NBLK, 256>>>();
    scanB_kernel<<<1, 512>>>();
    scanC_kernel<<<NBLK, 256>>>();
    scatter_kernel<<<(N_EDGES + 255) / 256, 256>>>(ei);
    nf_kernel<<<12500, 256>>>(x);
    h2pool_gemm<<<(N_NODES + 63) / 64, 256>>>(bat, W2l, b2, W2r, W1l, b1, W1r);
    final_kernel<<<N_GRAPHS, 32>>>(Wc, bc, out);
}